// round 8
// baseline (speedup 1.0000x reference)
#include <cuda_runtime.h>
#include <cstdint>

// SpikeFP8MulToFP32:
//   A, B: [N, 8] float 0/1 bit-vectors of fp8 e4m3 (order S,E3..E0,M2,M1,M0)
//   out : [N, 32] float 0/1 bit-vector of fp32(A_val * B_val), MSB (sign) first.
//
// Pure HBM streaming (268 MB in, 537 MB out). Plateau established at
// ~6.35 TB/s (77-79% DRAM) across 5 kernel shapes (SMEM stage / v8 / persistent
// pipeline / shuffle / 2x MLP) — including one at occ=54%, proving the memory
// system, not the SM, is the limiter (1:2 R/W turnaround ceiling).
// R8: leanest shape (shuffle, no SMEM/barrier) with ALL predication removed
// for the exact case N % 256 == 0 (true for this problem: 4194304 = 16384*256),
// default-policy stores (L2-batched writebacks). Guarded fallback kept for
// generality.

#define THREADS 256

static __device__ __forceinline__ uint32_t bit_of(float f) {
    // inputs are exactly 0.0f (0x00000000) or 1.0f (0x3F800000): test bit 23
    return (__float_as_uint(f) >> 23) & 1u;
}

static __device__ __forceinline__ float decode_e4m3(float4 lo, float4 hi) {
    // lo = {S, E3, E2, E1}, hi = {E0, M2, M1, M0}
    uint32_t s = bit_of(lo.x);
    uint32_t e = (bit_of(lo.y) << 3) | (bit_of(lo.z) << 2) |
                 (bit_of(lo.w) << 1) |  bit_of(hi.x);
    uint32_t m = (bit_of(hi.y) << 2) | (bit_of(hi.z) << 1) | bit_of(hi.w);
    // normal: (8+m)*2^(e-10); subnormal: m*2^-9
    uint32_t M = e ? (8u + m) : m;
    int      E = e ? ((int)e - 10) : -9;
    float mag = (float)(int)M * __int_as_float((E + 127) << 23);
    // OR sign in so zero products keep their sign bit (-0.0 matters to the
    // reference's fp32 bitcast)
    return __uint_as_float(__float_as_uint(mag) | (s << 31));
}

// expand bits [g_shift+3 .. g_shift] of t into a float4 of 0.0/1.0 (MSB first)
static __device__ __forceinline__ float4 expand4(uint32_t t) {
    float4 o;
    o.x = __uint_as_float(((t >> 3) & 1u) * 0x3F800000u);
    o.y = __uint_as_float(((t >> 2) & 1u) * 0x3F800000u);
    o.z = __uint_as_float(((t >> 1) & 1u) * 0x3F800000u);
    o.w = __uint_as_float(( t        & 1u) * 0x3F800000u);
    return o;
}

// ---- fast path: nrows % THREADS == 0, zero predication -------------------
__global__ void __launch_bounds__(THREADS)
spike_fp8_mul_exact(const float4* __restrict__ A4,
                    const float4* __restrict__ B4,
                    float4* __restrict__ out4) {
    const int tid  = threadIdx.x;
    const int lane = tid & 31;
    const int row  = blockIdx.x * THREADS + tid;

    const size_t r2 = 2 * (size_t)row;
    float4 a0 = __ldcs(&A4[r2]);
    float4 a1 = __ldcs(&A4[r2 + 1]);
    float4 b0 = __ldcs(&B4[r2]);
    float4 b1 = __ldcs(&B4[r2 + 1]);
    uint32_t p = __float_as_uint(decode_e4m3(a0, a1) * decode_e4m3(b0, b1));

    // warp covers 32 rows -> 4KB contiguous output, 8 coalesced 512B stores.
    // float4 q = k*32+lane of warp span: src row = k*4 + (lane>>3),
    // bit group = lane&7 (k*32 == 0 mod 8).
    float4* wout = out4 + (size_t)(row & ~31) * 8;
    const int g_shift  = 28 - ((lane & 7) << 2);
    const int src_base = lane >> 3;

#pragma unroll
    for (int k = 0; k < 8; k++) {
        uint32_t ps = __shfl_sync(0xffffffffu, p, k * 4 + src_base);
        wout[k * 32 + lane] = expand4(ps >> g_shift);
    }
}

// ---- generic guarded path (fallback, any nrows) --------------------------
__global__ void __launch_bounds__(THREADS)
spike_fp8_mul_guarded(const float4* __restrict__ A4,
                      const float4* __restrict__ B4,
                      float4* __restrict__ out4,
                      int nrows) {
    const int tid  = threadIdx.x;
    const int lane = tid & 31;
    const int row  = blockIdx.x * THREADS + tid;

    uint32_t p = 0;
    if (row < nrows) {
        size_t r2 = 2 * (size_t)row;
        float4 a0 = __ldcs(&A4[r2]);
        float4 a1 = __ldcs(&A4[r2 + 1]);
        float4 b0 = __ldcs(&B4[r2]);
        float4 b1 = __ldcs(&B4[r2 + 1]);
        p = __float_as_uint(decode_e4m3(a0, a1) * decode_e4m3(b0, b1));
    }

    const int warp_row0 = row & ~31;
    float4* wout = out4 + (size_t)warp_row0 * 8;
    const int rows_left = nrows - warp_row0;
    const int q_limit   = rows_left >= 32 ? 256 : rows_left * 8;
    const int g_shift   = 28 - ((lane & 7) << 2);
    const int src_base  = lane >> 3;

#pragma unroll
    for (int k = 0; k < 8; k++) {
        uint32_t ps = __shfl_sync(0xffffffffu, p, k * 4 + src_base);
        int q = k * 32 + lane;
        if (q < q_limit) wout[q] = expand4(ps >> g_shift);
    }
}

extern "C" void kernel_launch(void* const* d_in, const int* in_sizes, int n_in,
                              void* d_out, int out_size) {
    const float4* A4 = (const float4*)d_in[0];
    const float4* B4 = (const float4*)d_in[1];
    float4* out4 = (float4*)d_out;

    int nrows = in_sizes[0] / 8;
    if ((nrows & (THREADS - 1)) == 0) {
        spike_fp8_mul_exact<<<nrows / THREADS, THREADS>>>(A4, B4, out4);
    } else {
        int blocks = (nrows + THREADS - 1) / THREADS;
        spike_fp8_mul_guarded<<<blocks, THREADS>>>(A4, B4, out4, nrows);
    }
}

// round 9
// speedup vs baseline: 1.0193x; 1.0193x over previous
#include <cuda_runtime.h>
#include <cstdint>

// SpikeFP8MulToFP32:
//   A, B: [N, 8] float 0/1 bit-vectors of fp8 e4m3 (order S,E3..E0,M2,M1,M0)
//   out : [N, 32] float 0/1 bit-vector of fp32(A_val * B_val), MSB (sign) first.
//
// Pure HBM streaming: 268 MB in, 537 MB out, zero reuse. Session conclusion:
// six kernel shapes (SMEM stage / 256-bit v8 / persistent pipeline / warp
// shuffle / 2x-MLP / unguarded) ALL plateau at 77-79% DRAM (~6.35 TB/s),
// one of them at occ=54% — the limiter is the DRAM read/write turnaround for
// the 1:2 R:W mix, not anything SM-side. This file is the best-measured
// configuration (R1): 122.9us bench / 115.9us kernel / DRAM 78.8%.
//   - 1 thread = 1 row, 4x independent LDG.128 .cs (coalesced)
//   - decode fp8 in integer bits + 1 IEEE FMUL (exact; preserves -0.0)
//   - SMEM stage of product words, then 8x coalesced STG.128 .cs per thread

static __device__ __forceinline__ uint32_t bit_of(float f) {
    // inputs are exactly 0.0f (0x00000000) or 1.0f (0x3F800000): test bit 23
    return (__float_as_uint(f) >> 23) & 1u;
}

static __device__ __forceinline__ float decode_e4m3(float4 lo, float4 hi) {
    // lo = {S, E3, E2, E1}, hi = {E0, M2, M1, M0}
    uint32_t s = bit_of(lo.x);
    uint32_t e = (bit_of(lo.y) << 3) | (bit_of(lo.z) << 2) |
                 (bit_of(lo.w) << 1) |  bit_of(hi.x);
    uint32_t m = (bit_of(hi.y) << 2) | (bit_of(hi.z) << 1) | bit_of(hi.w);
    // normal:    (8+m) * 2^(e-10)
    // subnormal:  m    * 2^(-9)
    uint32_t M = e ? (8u + m) : m;
    int      E = e ? ((int)e - 10) : -9;
    float mag = (float)(int)M * __int_as_float((E + 127) << 23);
    // OR the sign in so M==0 yields a correctly signed zero (-0.0 matters:
    // the reference's fp32 bitcast exposes the sign bit of zero products)
    return __uint_as_float(__float_as_uint(mag) | (s << 31));
}

__global__ void __launch_bounds__(256)
spike_fp8_mul_kernel(const float4* __restrict__ A4,
                     const float4* __restrict__ B4,
                     float4* __restrict__ out4,
                     int nrows) {
    __shared__ uint32_t sh[256];

    const int tid = threadIdx.x;
    const int row = blockIdx.x * 256 + tid;

    uint32_t pbits = 0;
    if (row < nrows) {
        // each row = 8 floats = 2 float4
        float4 a0 = __ldcs(&A4[2 * row + 0]);
        float4 a1 = __ldcs(&A4[2 * row + 1]);
        float4 b0 = __ldcs(&B4[2 * row + 0]);
        float4 b1 = __ldcs(&B4[2 * row + 1]);
        float va = decode_e4m3(a0, a1);
        float vb = decode_e4m3(b0, b1);
        pbits = __float_as_uint(va * vb);   // exact in fp32; IEEE sign-of-zero
    }
    sh[tid] = pbits;
    __syncthreads();

    // Block writes 256 rows * 32 floats = 2048 float4, fully coalesced.
    // float4 q covers output floats [4q .. 4q+3] of this block's tile:
    //   local row = q>>3, bit group g = q&7, out[j] = bit (31-j) of p.
    const int rows_left = nrows - blockIdx.x * 256;      // >0
    const int q_limit   = rows_left >= 256 ? 2048 : rows_left * 8;
    float4* blk_out = out4 + (size_t)blockIdx.x * 2048;

    const int g_shift = 28 - ((tid & 7) << 2);           // invariant over k

#pragma unroll
    for (int k = 0; k < 8; k++) {
        int q = (k << 8) + tid;
        if (q < q_limit) {
            uint32_t p = sh[q >> 3];                     // 8-lane broadcast
            uint32_t t = p >> g_shift;                   // bits [31-4g .. 28-4g] in t[3..0]
            float4 v;
            v.x = __uint_as_float(((t >> 3) & 1u) * 0x3F800000u);
            v.y = __uint_as_float(((t >> 2) & 1u) * 0x3F800000u);
            v.z = __uint_as_float(((t >> 1) & 1u) * 0x3F800000u);
            v.w = __uint_as_float(( t        & 1u) * 0x3F800000u);
            __stcs(&blk_out[q], v);
        }
    }
}

extern "C" void kernel_launch(void* const* d_in, const int* in_sizes, int n_in,
                              void* d_out, int out_size) {
    const float4* A4 = (const float4*)d_in[0];
    const float4* B4 = (const float4*)d_in[1];
    float4* out4 = (float4*)d_out;

    int nrows = in_sizes[0] / 8;
    int blocks = (nrows + 255) / 256;
    spike_fp8_mul_kernel<<<blocks, 256>>>(A4, B4, out4, nrows);
}